// round 2
// baseline (speedup 1.0000x reference)
#include <cuda_runtime.h>
#include <cstdint>
#include <cstddef>

// Problem constants (match reference setup_inputs)
#define NN 50000
#define EE 640000
#define S_DIM 128
#define DN_DIM 128
#define DA_DIM 64
#define H1_DIM 512
#define THR2 (0.01f * 0.01f)
#define MAX_IT 10

// ---------------- scratch (__device__ globals; no allocation allowed) ------
__device__ float g_agg_arcs[NN * DA_DIM];
__device__ float g_agg_nodes[NN * DN_DIM];
__device__ float g_agg_states[NN * S_DIM];
__device__ float g_base[NN * H1_DIM];
__device__ float g_H[NN * H1_DIM];
__device__ float g_state[NN * S_DIM];
__device__ float g_state_old[NN * S_DIM];
__device__ float g_new[NN * S_DIM];
__device__ int   g_cnt[NN];
__device__ int   g_ptr_adj[NN + 1];
__device__ int   g_ptr_an[NN + 1];
__device__ int   g_src_adj[EE];
__device__ float g_val_adj[EE];
__device__ int   g_eid_an[EE];
__device__ float g_val_an[EE];
__device__ int   g_flag;
__device__ int   g_done;
__device__ int   g_cont;

// ---------------- helpers ---------------------------------------------------
__device__ __forceinline__ unsigned long long splat2(float x) {
    unsigned int u = __float_as_uint(x);
    return ((unsigned long long)u << 32) | (unsigned long long)u;
}
__device__ __forceinline__ float f2lo(unsigned long long v) {
    return __uint_as_float((unsigned int)(v & 0xffffffffull));
}
__device__ __forceinline__ float f2hi(unsigned long long v) {
    return __uint_as_float((unsigned int)(v >> 32));
}
#define FMA2(d, a, b) asm("fma.rn.f32x2 %0, %1, %2, %3;" : "=l"(d) : "l"(a), "l"(b), "l"(d))

// ---------------- CSR build -------------------------------------------------
__global__ void hist_kernel(const int* __restrict__ dst, int e) {
    int i = blockIdx.x * blockDim.x + threadIdx.x;
    if (i < e) atomicAdd(&g_cnt[dst[i]], 1);
}

__global__ void scan_kernel(const int* __restrict__ cnt, int* __restrict__ ptr, int n) {
    __shared__ int sh[1024];
    __shared__ int carry;
    int t = threadIdx.x;
    if (t == 0) { carry = 0; ptr[0] = 0; }
    __syncthreads();
    for (int base = 0; base < n; base += 1024) {
        int x = (base + t < n) ? cnt[base + t] : 0;
        sh[t] = x;
        __syncthreads();
        for (int off = 1; off < 1024; off <<= 1) {
            int y = (t >= off) ? sh[t - off] : 0;
            __syncthreads();
            sh[t] += y;
            __syncthreads();
        }
        if (base + t < n) ptr[base + t + 1] = carry + sh[t];
        __syncthreads();
        if (t == 0) carry += sh[1023];
        __syncthreads();
    }
}

__global__ void scatter_adj_kernel(const int* __restrict__ src, const int* __restrict__ dst,
                                   const float* __restrict__ vals, int e) {
    int i = blockIdx.x * blockDim.x + threadIdx.x;
    if (i < e) {
        int d = dst[i];
        int pos = g_ptr_adj[d] + atomicAdd(&g_cnt[d], 1);
        g_src_adj[pos] = src[i];
        g_val_adj[pos] = vals[i];
    }
}

__global__ void scatter_an_kernel(const int* __restrict__ dst, const float* __restrict__ vals, int e) {
    int i = blockIdx.x * blockDim.x + threadIdx.x;
    if (i < e) {
        int d = dst[i];
        int pos = g_ptr_an[d] + atomicAdd(&g_cnt[d], 1);
        g_eid_an[pos] = i;
        g_val_an[pos] = vals[i];
    }
}

// ---------------- SPMM ------------------------------------------------------
// out[dst] = sum_e vals[e] * dense[src[e]]  (128 features, warp per row)
__global__ void spmm128_kernel(const int* __restrict__ ptr, const int* __restrict__ srcs,
                               const float* __restrict__ vals, const float* __restrict__ dense,
                               float* __restrict__ out, int n, const int* gate) {
    if (gate && *gate == 0) return;
    int w = (blockIdx.x * blockDim.x + threadIdx.x) >> 5;
    int lane = threadIdx.x & 31;
    if (w >= n) return;
    int s = ptr[w], t = ptr[w + 1];
    float ax = 0.f, ay = 0.f, az = 0.f, aw = 0.f;
    for (int e = s; e < t; e++) {
        float v = vals[e];
        int src = srcs[e];
        float4 x = *(const float4*)(dense + (size_t)src * 128 + lane * 4);
        ax += v * x.x; ay += v * x.y; az += v * x.z; aw += v * x.w;
    }
    float4 o; o.x = ax; o.y = ay; o.z = az; o.w = aw;
    *(float4*)(out + (size_t)w * 128 + lane * 4) = o;
}

// agg_arcs: gather arcs rows (stride 66, offset 2), 64 features
__global__ void spmm_arcs_kernel(const float* __restrict__ arcs, int n) {
    int w = (blockIdx.x * blockDim.x + threadIdx.x) >> 5;
    int lane = threadIdx.x & 31;
    if (w >= n) return;
    int s = g_ptr_an[w], t = g_ptr_an[w + 1];
    float ax = 0.f, ay = 0.f;
    for (int e = s; e < t; e++) {
        float v = g_val_an[e];
        int eid = g_eid_an[e];
        float2 x = *(const float2*)(arcs + (size_t)eid * 66 + 2 + lane * 2);
        ax += v * x.x; ay += v * x.y;
    }
    float2 o; o.x = ax; o.y = ay;
    *(float2*)(g_agg_arcs + (size_t)w * 64 + lane * 2) = o;
}

// ---------------- state init / convergence / update ------------------------
__global__ void reset_kernel() {
    if (threadIdx.x == 0) { g_flag = 0; g_done = 0; g_cont = 0; }
}

__global__ void init_kernel(const float* __restrict__ si, int n) {
    int w = (blockIdx.x * blockDim.x + threadIdx.x) >> 5;
    int lane = threadIdx.x & 31;
    if (w >= n) return;
    float4 st = *(const float4*)(si + (size_t)w * 128 + lane * 4);
    *(float4*)(g_state + (size_t)w * 128 + lane * 4) = st;
    float4 one; one.x = one.y = one.z = one.w = 1.f;
    *(float4*)(g_state_old + (size_t)w * 128 + lane * 4) = one;
    float dx = st.x - 1.f, dy = st.y - 1.f, dz = st.z - 1.f, dw = st.w - 1.f;
    float d2 = dx * dx + dy * dy + dz * dz + dw * dw;
    #pragma unroll
    for (int s = 16; s > 0; s >>= 1) d2 += __shfl_xor_sync(0xffffffffu, d2, s);
    if (lane == 0 && d2 > THR2 * 128.f) atomicOr(&g_flag, 1);
}

__global__ void finalize_kernel() {
    if (threadIdx.x == 0) {
        int c = (g_flag && !g_done) ? 1 : 0;
        g_cont = c;
        g_done = c ? 0 : 1;
        g_flag = 0;
    }
}

__global__ void update_kernel(int n, const int* gate) {
    if (*gate == 0) return;
    int w = (blockIdx.x * blockDim.x + threadIdx.x) >> 5;
    int lane = threadIdx.x & 31;
    if (w >= n) return;
    float4 st = *(const float4*)(g_state + (size_t)w * 128 + lane * 4);
    float4 nw = *(const float4*)(g_new + (size_t)w * 128 + lane * 4);
    float dx = nw.x - st.x, dy = nw.y - st.y, dz = nw.z - st.z, dw = nw.w - st.w;
    float d2 = dx * dx + dy * dy + dz * dz + dw * dw;
    float n2 = st.x * st.x + st.y * st.y + st.z * st.z + st.w * st.w;
    #pragma unroll
    for (int s = 16; s > 0; s >>= 1) {
        d2 += __shfl_xor_sync(0xffffffffu, d2, s);
        n2 += __shfl_xor_sync(0xffffffffu, n2, s);
    }
    *(float4*)(g_state_old + (size_t)w * 128 + lane * 4) = st;
    *(float4*)(g_state + (size_t)w * 128 + lane * 4) = nw;
    if (lane == 0 && d2 > THR2 * n2) atomicOr(&g_flag, 1);
}

// ---------------- GEMM (fp32, packed f32x2 FMA) -----------------------------
// C[M x Nout] = act( addend + bias + sum_segs A_s @ B_s )
// BM=BN=128, BK=16, 256 threads, 8x8 micro-tile, acc pairs packed along N.
__global__ void __launch_bounds__(256, 2) gemm_kernel(
    int M,
    const float* __restrict__ A0, int lda0, const float* __restrict__ B0, int K0,
    const float* __restrict__ A1, int lda1, const float* __restrict__ B1, int K1,
    const float* __restrict__ A2, int lda2, const float* __restrict__ B2, int K2,
    int ldb,
    const float* __restrict__ addend, int ldadd,
    const float* __restrict__ bias,
    int do_tanh,
    float* __restrict__ C, int ldc,
    const int* gate)
{
    if (gate && *gate == 0) return;
    __shared__ unsigned long long As2[16][129];  // pre-splatted A, padded stride
    __shared__ float Bs[16][128];

    const int bm = blockIdx.x * 128;
    const int bn = blockIdx.y * 128;
    const int tid = threadIdx.x;
    const int tx = tid & 15;
    const int ty = tid >> 4;

    unsigned long long acc[8][4];
    #pragma unroll
    for (int i = 0; i < 8; i++)
        #pragma unroll
        for (int j = 0; j < 4; j++) acc[i][j] = 0ull;

    const int a_row = tid >> 1;
    const int a_f = (tid & 1) * 2;
    const int b_k0 = (tid >> 5) * 2;
    const int lane = tid & 31;
    const int grow = bm + a_row;
    const bool arow_ok = grow < M;

    auto do_seg = [&](const float* __restrict__ A, int lda,
                      const float* __restrict__ B, int K) {
        for (int kb = 0; kb < K; kb += 16) {
            #pragma unroll
            for (int c = 0; c < 2; c++) {
                int f = a_f + c;
                float4 av = make_float4(0.f, 0.f, 0.f, 0.f);
                if (arow_ok) av = *(const float4*)(A + (size_t)grow * lda + kb + f * 4);
                As2[f * 4 + 0][a_row] = splat2(av.x);
                As2[f * 4 + 1][a_row] = splat2(av.y);
                As2[f * 4 + 2][a_row] = splat2(av.z);
                As2[f * 4 + 3][a_row] = splat2(av.w);
            }
            #pragma unroll
            for (int r = 0; r < 2; r++) {
                int kk = b_k0 + r;
                *(float4*)&Bs[kk][lane * 4] =
                    *(const float4*)(B + (size_t)(kb + kk) * ldb + bn + lane * 4);
            }
            __syncthreads();
            #pragma unroll
            for (int k = 0; k < 16; k++) {
                unsigned long long a2[8], b2[4];
                #pragma unroll
                for (int i = 0; i < 8; i++) a2[i] = As2[k][ty * 8 + i];
                b2[0] = *(const unsigned long long*)&Bs[k][tx * 4];
                b2[1] = *(const unsigned long long*)&Bs[k][tx * 4 + 2];
                b2[2] = *(const unsigned long long*)&Bs[k][tx * 4 + 64];
                b2[3] = *(const unsigned long long*)&Bs[k][tx * 4 + 66];
                #pragma unroll
                for (int i = 0; i < 8; i++) {
                    FMA2(acc[i][0], a2[i], b2[0]);
                    FMA2(acc[i][1], a2[i], b2[1]);
                    FMA2(acc[i][2], a2[i], b2[2]);
                    FMA2(acc[i][3], a2[i], b2[3]);
                }
            }
            __syncthreads();
        }
    };

    do_seg(A0, lda0, B0, K0);
    if (K1) do_seg(A1, lda1, B1, K1);
    if (K2) do_seg(A2, lda2, B2, K2);

    #pragma unroll
    for (int i = 0; i < 8; i++) {
        int row = bm + ty * 8 + i;
        if (row >= M) break;
        #pragma unroll
        for (int h = 0; h < 2; h++) {
            int col = bn + h * 64 + tx * 4;
            float4 v;
            v.x = f2lo(acc[i][h * 2]);     v.y = f2hi(acc[i][h * 2]);
            v.z = f2lo(acc[i][h * 2 + 1]); v.w = f2hi(acc[i][h * 2 + 1]);
            if (addend) {
                float4 b = *(const float4*)(addend + (size_t)row * ldadd + col);
                v.x += b.x; v.y += b.y; v.z += b.z; v.w += b.w;
            }
            if (bias) {
                float4 b = *(const float4*)(bias + col);
                v.x += b.x; v.y += b.y; v.z += b.z; v.w += b.w;
            }
            if (do_tanh) {
                v.x = tanhf(v.x); v.y = tanhf(v.y); v.z = tanhf(v.z); v.w = tanhf(v.w);
            }
            *(float4*)(C + (size_t)row * ldc + col) = v;
        }
    }
}

// ---------------- final projection (N x 512 @ 512 x 7) ----------------------
// Masks are int32 (JAX bool inputs are materialized as 4-byte ints by the harness).
__global__ void out_kernel(const float* __restrict__ Hout, const float* __restrict__ Wo2,
                           const float* __restrict__ bo2, const int* __restrict__ m1,
                           const int* __restrict__ m2, float* __restrict__ out, int n) {
    __shared__ float w[512 * 7];
    for (int i = threadIdx.x; i < 512 * 7; i += blockDim.x) w[i] = Wo2[i];
    __syncthreads();
    int wrp = (blockIdx.x * blockDim.x + threadIdx.x) >> 5;
    int lane = threadIdx.x & 31;
    if (wrp >= n) return;
    const float* h = Hout + (size_t)wrp * 512;
    float acc[7] = {0.f, 0.f, 0.f, 0.f, 0.f, 0.f, 0.f};
    for (int t = 0; t < 16; t++) {
        int k = t * 32 + lane;
        float x = h[k];
        #pragma unroll
        for (int o = 0; o < 7; o++) acc[o] += x * w[k * 7 + o];
    }
    #pragma unroll
    for (int o = 0; o < 7; o++) {
        #pragma unroll
        for (int s = 16; s > 0; s >>= 1) acc[o] += __shfl_xor_sync(0xffffffffu, acc[o], s);
    }
    if (lane == 0) {
        float mk = (m1[wrp] != 0 && m2[wrp] != 0) ? 1.f : 0.f;
        #pragma unroll
        for (int o = 0; o < 7; o++) out[(size_t)wrp * 7 + o] = (acc[o] + bo2[o]) * mk;
    }
}

// ---------------- host ------------------------------------------------------
extern "C" void kernel_launch(void* const* d_in, const int* in_sizes, int n_in,
                              void* d_out, int out_size) {
    const float*   nodes      = (const float*)d_in[0];
    const float*   arcs       = (const float*)d_in[1];
    const int*     set_mask   = (const int*)d_in[2];
    const int*     output_mask= (const int*)d_in[3];
    const int*     adj_src    = (const int*)d_in[4];
    const int*     adj_dst    = (const int*)d_in[5];
    const float*   adj_vals   = (const float*)d_in[6];
    const int*     an_dst     = (const int*)d_in[7];
    const float*   an_vals    = (const float*)d_in[8];
    const float*   state_init = (const float*)d_in[9];
    const float*   Ws1        = (const float*)d_in[10];
    const float*   bs1        = (const float*)d_in[11];
    const float*   Ws2        = (const float*)d_in[12];
    const float*   bs2        = (const float*)d_in[13];
    const float*   Wo1        = (const float*)d_in[14];
    const float*   bo1        = (const float*)d_in[15];
    const float*   Wo2        = (const float*)d_in[16];
    const float*   bo2        = (const float*)d_in[17];

    const int n = NN;
    const int e = EE;

    // device pointers to scratch symbols
    float *p_agg_arcs, *p_agg_nodes, *p_agg_states, *p_base, *p_H, *p_state, *p_new;
    int *p_cnt, *p_ptr_adj, *p_ptr_an, *p_src_adj, *p_cont;
    float *p_val_adj;
    cudaGetSymbolAddress((void**)&p_agg_arcs, g_agg_arcs);
    cudaGetSymbolAddress((void**)&p_agg_nodes, g_agg_nodes);
    cudaGetSymbolAddress((void**)&p_agg_states, g_agg_states);
    cudaGetSymbolAddress((void**)&p_base, g_base);
    cudaGetSymbolAddress((void**)&p_H, g_H);
    cudaGetSymbolAddress((void**)&p_state, g_state);
    cudaGetSymbolAddress((void**)&p_new, g_new);
    cudaGetSymbolAddress((void**)&p_cnt, g_cnt);
    cudaGetSymbolAddress((void**)&p_ptr_adj, g_ptr_adj);
    cudaGetSymbolAddress((void**)&p_ptr_an, g_ptr_an);
    cudaGetSymbolAddress((void**)&p_src_adj, g_src_adj);
    cudaGetSymbolAddress((void**)&p_val_adj, g_val_adj);
    cudaGetSymbolAddress((void**)&p_cont, g_cont);

    const int gbE = (e + 255) / 256;
    const int gbW = (n * 32 + 255) / 256;  // warp-per-row kernels
    const int gbM = (n + 127) / 128;       // GEMM row blocks

    // Ws1 row-block sub-matrices: [state | nodes | agg_states | agg_nodes | agg_arcs]
    const float* W_state = Ws1;
    const float* W_nodes = Ws1 + 128 * 512;
    const float* W_aggst = Ws1 + 256 * 512;
    const float* W_aggnd = Ws1 + 384 * 512;
    const float* W_aggar = Ws1 + 512 * 512;

    // ---- CSR for an_dst (arc aggregation), then adj_dst ----
    cudaMemsetAsync(p_cnt, 0, n * sizeof(int));
    hist_kernel<<<gbE, 256>>>(an_dst, e);
    scan_kernel<<<1, 1024>>>(p_cnt, p_ptr_an, n);
    cudaMemsetAsync(p_cnt, 0, n * sizeof(int));
    scatter_an_kernel<<<gbE, 256>>>(an_dst, an_vals, e);

    cudaMemsetAsync(p_cnt, 0, n * sizeof(int));
    hist_kernel<<<gbE, 256>>>(adj_dst, e);
    scan_kernel<<<1, 1024>>>(p_cnt, p_ptr_adj, n);
    cudaMemsetAsync(p_cnt, 0, n * sizeof(int));
    scatter_adj_kernel<<<gbE, 256>>>(adj_src, adj_dst, adj_vals, e);

    // ---- loop-invariant aggregations ----
    spmm_arcs_kernel<<<gbW, 256>>>(arcs, n);
    spmm128_kernel<<<gbW, 256>>>(p_ptr_adj, p_src_adj, p_val_adj, nodes, p_agg_nodes, n, nullptr);

    // ---- state init + invariant part of GEMM1 ----
    reset_kernel<<<1, 32>>>();
    init_kernel<<<gbW, 256>>>(state_init, n);
    gemm_kernel<<<dim3(gbM, 4), 256>>>(
        n,
        nodes, 128, W_nodes, 128,
        p_agg_nodes, 128, W_aggnd, 128,
        p_agg_arcs, 64, W_aggar, 64,
        512,
        nullptr, 0, bs1, 0,
        p_base, 512, nullptr);

    // ---- fixed-point iterations ----
    for (int it = 0; it < MAX_IT; it++) {
        finalize_kernel<<<1, 32>>>();
        spmm128_kernel<<<gbW, 256>>>(p_ptr_adj, p_src_adj, p_val_adj, p_state, p_agg_states, n, p_cont);
        gemm_kernel<<<dim3(gbM, 4), 256>>>(
            n,
            p_state, 128, W_state, 128,
            p_agg_states, 128, W_aggst, 128,
            nullptr, 0, nullptr, 0,
            512,
            p_base, 512, nullptr, 1,
            p_H, 512, p_cont);
        gemm_kernel<<<dim3(gbM, 1), 256>>>(
            n,
            p_H, 512, Ws2, 512,
            nullptr, 0, nullptr, 0,
            nullptr, 0, nullptr, 0,
            128,
            nullptr, 0, bs2, 1,
            p_new, 128, p_cont);
        update_kernel<<<gbW, 256>>>(n, p_cont);
    }

    // ---- output head ----
    gemm_kernel<<<dim3(gbM, 4), 256>>>(
        n,
        p_state, 128, Wo1, 128,
        nodes, 128, Wo1 + 128 * 512, 128,
        nullptr, 0, nullptr, 0,
        512,
        nullptr, 0, bo1, 1,
        p_H, 512, nullptr);
    out_kernel<<<gbW, 256>>>(p_H, Wo2, bo2, set_mask, output_mask, (float*)d_out, n);
}

// round 3
// speedup vs baseline: 1.0021x; 1.0021x over previous
#include <cuda_runtime.h>
#include <cstdint>
#include <cstddef>

// Problem constants (match reference setup_inputs)
#define NN 50000
#define EE 640000
#define S_DIM 128
#define DN_DIM 128
#define DA_DIM 64
#define H1_DIM 512
#define THR2 (0.01f * 0.01f)
#define MAX_IT 10

// ---------------- scratch (__device__ globals; no allocation allowed) ------
__device__ float g_agg_arcs[NN * DA_DIM];
__device__ float g_agg_nodes[NN * DN_DIM];
__device__ float g_agg_states[NN * S_DIM];
__device__ float g_base[NN * H1_DIM];
__device__ float g_H[NN * H1_DIM];
__device__ float g_state[NN * S_DIM];
__device__ float g_state_old[NN * S_DIM];
__device__ float g_new[NN * S_DIM];
__device__ int   g_cnt[NN];
__device__ int   g_ptr_adj[NN + 1];
__device__ int   g_ptr_an[NN + 1];
__device__ int   g_src_adj[EE];
__device__ float g_val_adj[EE];
__device__ int   g_eid_an[EE];
__device__ float g_val_an[EE];
__device__ int   g_flag;
__device__ int   g_done;
__device__ int   g_cont;

// ---------------- helpers ---------------------------------------------------
__device__ __forceinline__ unsigned long long splat2(float x) {
    unsigned int u = __float_as_uint(x);
    return ((unsigned long long)u << 32) | (unsigned long long)u;
}
__device__ __forceinline__ float f2lo(unsigned long long v) {
    return __uint_as_float((unsigned int)(v & 0xffffffffull));
}
__device__ __forceinline__ float f2hi(unsigned long long v) {
    return __uint_as_float((unsigned int)(v >> 32));
}
#define FMA2(d, a, b) asm("fma.rn.f32x2 %0, %1, %2, %3;" : "=l"(d) : "l"(a), "l"(b), "l"(d))

// ---------------- CSR build -------------------------------------------------
__global__ void hist_kernel(const int* __restrict__ dst, int e) {
    int i = blockIdx.x * blockDim.x + threadIdx.x;
    if (i < e) atomicAdd(&g_cnt[dst[i]], 1);
}

__global__ void scan_kernel(const int* __restrict__ cnt, int* __restrict__ ptr, int n) {
    __shared__ int sh[1024];
    __shared__ int carry;
    int t = threadIdx.x;
    if (t == 0) { carry = 0; ptr[0] = 0; }
    __syncthreads();
    for (int base = 0; base < n; base += 1024) {
        int x = (base + t < n) ? cnt[base + t] : 0;
        sh[t] = x;
        __syncthreads();
        for (int off = 1; off < 1024; off <<= 1) {
            int y = (t >= off) ? sh[t - off] : 0;
            __syncthreads();
            sh[t] += y;
            __syncthreads();
        }
        if (base + t < n) ptr[base + t + 1] = carry + sh[t];
        __syncthreads();
        if (t == 0) carry += sh[1023];
        __syncthreads();
    }
}

__global__ void scatter_adj_kernel(const int* __restrict__ src, const int* __restrict__ dst,
                                   const float* __restrict__ vals, int e) {
    int i = blockIdx.x * blockDim.x + threadIdx.x;
    if (i < e) {
        int d = dst[i];
        int pos = g_ptr_adj[d] + atomicAdd(&g_cnt[d], 1);
        g_src_adj[pos] = src[i];
        g_val_adj[pos] = vals[i];
    }
}

__global__ void scatter_an_kernel(const int* __restrict__ dst, const float* __restrict__ vals, int e) {
    int i = blockIdx.x * blockDim.x + threadIdx.x;
    if (i < e) {
        int d = dst[i];
        int pos = g_ptr_an[d] + atomicAdd(&g_cnt[d], 1);
        g_eid_an[pos] = i;
        g_val_an[pos] = vals[i];
    }
}

// ---------------- SPMM ------------------------------------------------------
__global__ void spmm128_kernel(const int* __restrict__ ptr, const int* __restrict__ srcs,
                               const float* __restrict__ vals, const float* __restrict__ dense,
                               float* __restrict__ out, int n, const int* gate) {
    if (gate && *gate == 0) return;
    int w = (blockIdx.x * blockDim.x + threadIdx.x) >> 5;
    int lane = threadIdx.x & 31;
    if (w >= n) return;
    int s = ptr[w], t = ptr[w + 1];
    float ax = 0.f, ay = 0.f, az = 0.f, aw = 0.f;
    for (int e = s; e < t; e++) {
        float v = vals[e];
        int src = srcs[e];
        float4 x = *(const float4*)(dense + (size_t)src * 128 + lane * 4);
        ax += v * x.x; ay += v * x.y; az += v * x.z; aw += v * x.w;
    }
    float4 o; o.x = ax; o.y = ay; o.z = az; o.w = aw;
    *(float4*)(out + (size_t)w * 128 + lane * 4) = o;
}

__global__ void spmm_arcs_kernel(const float* __restrict__ arcs, int n) {
    int w = (blockIdx.x * blockDim.x + threadIdx.x) >> 5;
    int lane = threadIdx.x & 31;
    if (w >= n) return;
    int s = g_ptr_an[w], t = g_ptr_an[w + 1];
    float ax = 0.f, ay = 0.f;
    for (int e = s; e < t; e++) {
        float v = g_val_an[e];
        int eid = g_eid_an[e];
        float2 x = *(const float2*)(arcs + (size_t)eid * 66 + 2 + lane * 2);
        ax += v * x.x; ay += v * x.y;
    }
    float2 o; o.x = ax; o.y = ay;
    *(float2*)(g_agg_arcs + (size_t)w * 64 + lane * 2) = o;
}

// ---------------- state init / convergence / update ------------------------
__global__ void reset_kernel() {
    if (threadIdx.x == 0) { g_flag = 0; g_done = 0; g_cont = 0; }
}

__global__ void init_kernel(const float* __restrict__ si, int n) {
    int w = (blockIdx.x * blockDim.x + threadIdx.x) >> 5;
    int lane = threadIdx.x & 31;
    if (w >= n) return;
    float4 st = *(const float4*)(si + (size_t)w * 128 + lane * 4);
    *(float4*)(g_state + (size_t)w * 128 + lane * 4) = st;
    float4 one; one.x = one.y = one.z = one.w = 1.f;
    *(float4*)(g_state_old + (size_t)w * 128 + lane * 4) = one;
    float dx = st.x - 1.f, dy = st.y - 1.f, dz = st.z - 1.f, dw = st.w - 1.f;
    float d2 = dx * dx + dy * dy + dz * dz + dw * dw;
    #pragma unroll
    for (int s = 16; s > 0; s >>= 1) d2 += __shfl_xor_sync(0xffffffffu, d2, s);
    if (lane == 0 && d2 > THR2 * 128.f) atomicOr(&g_flag, 1);
}

__global__ void finalize_kernel() {
    if (threadIdx.x == 0) {
        int c = (g_flag && !g_done) ? 1 : 0;
        g_cont = c;
        g_done = c ? 0 : 1;
        g_flag = 0;
    }
}

__global__ void update_kernel(int n, const int* gate) {
    if (*gate == 0) return;
    int w = (blockIdx.x * blockDim.x + threadIdx.x) >> 5;
    int lane = threadIdx.x & 31;
    if (w >= n) return;
    float4 st = *(const float4*)(g_state + (size_t)w * 128 + lane * 4);
    float4 nw = *(const float4*)(g_new + (size_t)w * 128 + lane * 4);
    float dx = nw.x - st.x, dy = nw.y - st.y, dz = nw.z - st.z, dw = nw.w - st.w;
    float d2 = dx * dx + dy * dy + dz * dz + dw * dw;
    float n2 = st.x * st.x + st.y * st.y + st.z * st.z + st.w * st.w;
    #pragma unroll
    for (int s = 16; s > 0; s >>= 1) {
        d2 += __shfl_xor_sync(0xffffffffu, d2, s);
        n2 += __shfl_xor_sync(0xffffffffu, n2, s);
    }
    *(float4*)(g_state_old + (size_t)w * 128 + lane * 4) = st;
    *(float4*)(g_state + (size_t)w * 128 + lane * 4) = nw;
    if (lane == 0 && d2 > THR2 * n2) atomicOr(&g_flag, 1);
}

// ---------------- GEMM v2: crossbar-balanced f32x2, double-buffered --------
// C[M x Nout] = act( addend + bias + sum_segs A_s @ B_s )
// BM=128, BN=NPAIRS*32 (256 or 128), BK=16, 256 threads.
// Per thread: 8 rows x NPAIRS col-pairs; acc packed along N (f32x2).
// A: 2x LDS.128 (warp-broadcast) + register splat. B: conflict-free LDS.64.
template<int NPAIRS>
__global__ void __launch_bounds__(256) gemm2_kernel(
    int M,
    const float* __restrict__ A0, int lda0, const float* __restrict__ B0, int K0,
    const float* __restrict__ A1, int lda1, const float* __restrict__ B1, int K1,
    const float* __restrict__ A2, int lda2, const float* __restrict__ B2, int K2,
    int ldb,
    const float* __restrict__ addend, int ldadd,
    const float* __restrict__ bias,
    int do_tanh,
    float* __restrict__ C, int ldc,
    const int* gate)
{
    constexpr int BN = NPAIRS * 32;
    constexpr int BK = 16;
    constexpr int BL4 = BN / 64;          // B float4s per thread (4 or 2)
    __shared__ float As[2][BK][128];
    __shared__ float Bs[2][BK][BN];

    if (gate && *gate == 0) return;

    const int tid = threadIdx.x;
    const int tx = tid & 15;
    const int ty = tid >> 4;
    const int bm = blockIdx.x * 128;
    const int bn = blockIdx.y * BN;

    // A loader: thread covers row ar, k-cols [af, af+8)
    const int ar = tid >> 1;
    const int af = (tid & 1) * 8;
    const int grow = bm + ar;
    const bool arow_ok = grow < M;
    // B loader: thread covers k-row br, cols [bc, bc + BN/16)
    const int br = tid >> 4;
    const int bc = (tid & 15) * (BN / 16);

    unsigned long long acc[8][NPAIRS];
    #pragma unroll
    for (int i = 0; i < 8; i++)
        #pragma unroll
        for (int j = 0; j < NPAIRS; j++) acc[i][j] = 0ull;

    const float* segA[3] = {A0, A1, A2};
    const float* segB[3] = {B0, B1, B2};
    int segLda[3] = {lda0, lda1, lda2};
    int segK[3] = {K0, K1, K2};

    float4 pa0, pa1, pb[BL4];

    auto load_tile = [&](int s, int kb) {
        const float* A = segA[s];
        const float* B = segB[s];
        int lda = segLda[s];
        if (arow_ok) {
            pa0 = *(const float4*)(A + (size_t)grow * lda + kb + af);
            pa1 = *(const float4*)(A + (size_t)grow * lda + kb + af + 4);
        } else {
            pa0 = make_float4(0.f, 0.f, 0.f, 0.f);
            pa1 = pa0;
        }
        #pragma unroll
        for (int c = 0; c < BL4; c++)
            pb[c] = *(const float4*)(B + (size_t)(kb + br) * ldb + bn + bc + 4 * c);
    };

    auto stage = [&](int buf) {
        As[buf][af + 0][ar] = pa0.x;
        As[buf][af + 1][ar] = pa0.y;
        As[buf][af + 2][ar] = pa0.z;
        As[buf][af + 3][ar] = pa0.w;
        As[buf][af + 4][ar] = pa1.x;
        As[buf][af + 5][ar] = pa1.y;
        As[buf][af + 6][ar] = pa1.z;
        As[buf][af + 7][ar] = pa1.w;
        #pragma unroll
        for (int c = 0; c < BL4; c++)
            *(float4*)&Bs[buf][br][bc + 4 * c] = pb[c];
    };

    auto compute = [&](int buf) {
        #pragma unroll
        for (int k = 0; k < BK; k++) {
            float4 av0 = *(const float4*)&As[buf][k][ty * 8];
            float4 av1 = *(const float4*)&As[buf][k][ty * 8 + 4];
            unsigned long long a2[8];
            a2[0] = splat2(av0.x); a2[1] = splat2(av0.y);
            a2[2] = splat2(av0.z); a2[3] = splat2(av0.w);
            a2[4] = splat2(av1.x); a2[5] = splat2(av1.y);
            a2[6] = splat2(av1.z); a2[7] = splat2(av1.w);
            unsigned long long b2[NPAIRS];
            #pragma unroll
            for (int j = 0; j < NPAIRS; j++)
                b2[j] = *(const unsigned long long*)&Bs[buf][k][2 * tx + 32 * j];
            #pragma unroll
            for (int i = 0; i < 8; i++)
                #pragma unroll
                for (int j = 0; j < NPAIRS; j++)
                    FMA2(acc[i][j], a2[i], b2[j]);
        }
    };

    // double-buffered mainloop over flattened (segment, kb) tiles
    int s = 0, kb = 0;
    load_tile(s, kb);
    stage(0);
    __syncthreads();
    int buf = 0;
    while (true) {
        // advance to next tile
        int ns = s, nkb = kb + BK;
        while (ns < 3 && nkb >= segK[ns]) { ns++; nkb = 0; }
        bool has_next = (ns < 3) && (segK[ns] > 0);
        if (has_next) load_tile(ns, nkb);
        compute(buf);
        if (!has_next) break;
        stage(buf ^ 1);
        __syncthreads();
        buf ^= 1;
        s = ns; kb = nkb;
    }

    // epilogue
    #pragma unroll
    for (int i = 0; i < 8; i++) {
        int row = bm + ty * 8 + i;
        if (row >= M) break;
        #pragma unroll
        for (int j = 0; j < NPAIRS; j++) {
            int col = bn + 2 * tx + 32 * j;
            float2 v;
            v.x = f2lo(acc[i][j]);
            v.y = f2hi(acc[i][j]);
            if (addend) {
                float2 b = *(const float2*)(addend + (size_t)row * ldadd + col);
                v.x += b.x; v.y += b.y;
            }
            if (bias) {
                float2 b = *(const float2*)(bias + col);
                v.x += b.x; v.y += b.y;
            }
            if (do_tanh) { v.x = tanhf(v.x); v.y = tanhf(v.y); }
            *(float2*)(C + (size_t)row * ldc + col) = v;
        }
    }
}

// ---------------- final projection (N x 512 @ 512 x 7) ----------------------
__global__ void out_kernel(const float* __restrict__ Hout, const float* __restrict__ Wo2,
                           const float* __restrict__ bo2, const int* __restrict__ m1,
                           const int* __restrict__ m2, float* __restrict__ out, int n) {
    __shared__ float w[512 * 7];
    for (int i = threadIdx.x; i < 512 * 7; i += blockDim.x) w[i] = Wo2[i];
    __syncthreads();
    int wrp = (blockIdx.x * blockDim.x + threadIdx.x) >> 5;
    int lane = threadIdx.x & 31;
    if (wrp >= n) return;
    const float* h = Hout + (size_t)wrp * 512;
    float acc[7] = {0.f, 0.f, 0.f, 0.f, 0.f, 0.f, 0.f};
    for (int t = 0; t < 16; t++) {
        int k = t * 32 + lane;
        float x = h[k];
        #pragma unroll
        for (int o = 0; o < 7; o++) acc[o] += x * w[k * 7 + o];
    }
    #pragma unroll
    for (int o = 0; o < 7; o++) {
        #pragma unroll
        for (int s = 16; s > 0; s >>= 1) acc[o] += __shfl_xor_sync(0xffffffffu, acc[o], s);
    }
    if (lane == 0) {
        float mk = (m1[wrp] != 0 && m2[wrp] != 0) ? 1.f : 0.f;
        #pragma unroll
        for (int o = 0; o < 7; o++) out[(size_t)wrp * 7 + o] = (acc[o] + bo2[o]) * mk;
    }
}

// ---------------- host ------------------------------------------------------
extern "C" void kernel_launch(void* const* d_in, const int* in_sizes, int n_in,
                              void* d_out, int out_size) {
    const float*   nodes      = (const float*)d_in[0];
    const float*   arcs       = (const float*)d_in[1];
    const int*     set_mask   = (const int*)d_in[2];
    const int*     output_mask= (const int*)d_in[3];
    const int*     adj_src    = (const int*)d_in[4];
    const int*     adj_dst    = (const int*)d_in[5];
    const float*   adj_vals   = (const float*)d_in[6];
    const int*     an_dst     = (const int*)d_in[7];
    const float*   an_vals    = (const float*)d_in[8];
    const float*   state_init = (const float*)d_in[9];
    const float*   Ws1        = (const float*)d_in[10];
    const float*   bs1        = (const float*)d_in[11];
    const float*   Ws2        = (const float*)d_in[12];
    const float*   bs2        = (const float*)d_in[13];
    const float*   Wo1        = (const float*)d_in[14];
    const float*   bo1        = (const float*)d_in[15];
    const float*   Wo2        = (const float*)d_in[16];
    const float*   bo2        = (const float*)d_in[17];

    const int n = NN;
    const int e = EE;

    float *p_agg_arcs, *p_agg_nodes, *p_agg_states, *p_base, *p_H, *p_state, *p_new;
    int *p_cnt, *p_ptr_adj, *p_ptr_an, *p_src_adj, *p_cont;
    float *p_val_adj;
    cudaGetSymbolAddress((void**)&p_agg_arcs, g_agg_arcs);
    cudaGetSymbolAddress((void**)&p_agg_nodes, g_agg_nodes);
    cudaGetSymbolAddress((void**)&p_agg_states, g_agg_states);
    cudaGetSymbolAddress((void**)&p_base, g_base);
    cudaGetSymbolAddress((void**)&p_H, g_H);
    cudaGetSymbolAddress((void**)&p_state, g_state);
    cudaGetSymbolAddress((void**)&p_new, g_new);
    cudaGetSymbolAddress((void**)&p_cnt, g_cnt);
    cudaGetSymbolAddress((void**)&p_ptr_adj, g_ptr_adj);
    cudaGetSymbolAddress((void**)&p_ptr_an, g_ptr_an);
    cudaGetSymbolAddress((void**)&p_src_adj, g_src_adj);
    cudaGetSymbolAddress((void**)&p_val_adj, g_val_adj);
    cudaGetSymbolAddress((void**)&p_cont, g_cont);

    const int gbE = (e + 255) / 256;
    const int gbW = (n * 32 + 255) / 256;
    const int gbM = (n + 127) / 128;

    // Ws1 row-block sub-matrices: [state | nodes | agg_states | agg_nodes | agg_arcs]
    const float* W_state = Ws1;
    const float* W_nodes = Ws1 + 128 * 512;
    const float* W_aggst = Ws1 + 256 * 512;
    const float* W_aggnd = Ws1 + 384 * 512;
    const float* W_aggar = Ws1 + 512 * 512;

    // ---- CSR builds ----
    cudaMemsetAsync(p_cnt, 0, n * sizeof(int));
    hist_kernel<<<gbE, 256>>>(an_dst, e);
    scan_kernel<<<1, 1024>>>(p_cnt, p_ptr_an, n);
    cudaMemsetAsync(p_cnt, 0, n * sizeof(int));
    scatter_an_kernel<<<gbE, 256>>>(an_dst, an_vals, e);

    cudaMemsetAsync(p_cnt, 0, n * sizeof(int));
    hist_kernel<<<gbE, 256>>>(adj_dst, e);
    scan_kernel<<<1, 1024>>>(p_cnt, p_ptr_adj, n);
    cudaMemsetAsync(p_cnt, 0, n * sizeof(int));
    scatter_adj_kernel<<<gbE, 256>>>(adj_src, adj_dst, adj_vals, e);

    // ---- loop-invariant aggregations ----
    spmm_arcs_kernel<<<gbW, 256>>>(arcs, n);
    spmm128_kernel<<<gbW, 256>>>(p_ptr_adj, p_src_adj, p_val_adj, nodes, p_agg_nodes, n, nullptr);

    // ---- state init + invariant part of GEMM1 ----
    reset_kernel<<<1, 32>>>();
    init_kernel<<<gbW, 256>>>(state_init, n);
    gemm2_kernel<8><<<dim3(gbM, 2), 256>>>(
        n,
        nodes, 128, W_nodes, 128,
        p_agg_nodes, 128, W_aggnd, 128,
        p_agg_arcs, 64, W_aggar, 64,
        512,
        nullptr, 0, bs1, 0,
        p_base, 512, nullptr);

    // ---- fixed-point iterations ----
    for (int it = 0; it < MAX_IT; it++) {
        finalize_kernel<<<1, 32>>>();
        spmm128_kernel<<<gbW, 256>>>(p_ptr_adj, p_src_adj, p_val_adj, p_state, p_agg_states, n, p_cont);
        gemm2_kernel<8><<<dim3(gbM, 2), 256>>>(
            n,
            p_state, 128, W_state, 128,
            p_agg_states, 128, W_aggst, 128,
            nullptr, 0, nullptr, 0,
            512,
            p_base, 512, nullptr, 1,
            p_H, 512, p_cont);
        gemm2_kernel<4><<<dim3(gbM, 1), 256>>>(
            n,
            p_H, 512, Ws2, 512,
            nullptr, 0, nullptr, 0,
            nullptr, 0, nullptr, 0,
            128,
            nullptr, 0, bs2, 1,
            p_new, 128, p_cont);
        update_kernel<<<gbW, 256>>>(n, p_cont);
    }

    // ---- output head ----
    gemm2_kernel<8><<<dim3(gbM, 2), 256>>>(
        n,
        p_state, 128, Wo1, 128,
        nodes, 128, Wo1 + 128 * 512, 128,
        nullptr, 0, nullptr, 0,
        512,
        nullptr, 0, bo1, 1,
        p_H, 512, nullptr);
    out_kernel<<<gbW, 256>>>(p_H, Wo2, bo2, set_mask, output_mask, (float*)d_out, n);
}

// round 5
// speedup vs baseline: 1.2848x; 1.2821x over previous
#include <cuda_runtime.h>
#include <cuda_bf16.h>
#include <cstdint>
#include <cstddef>

#define NN 50000
#define EE 640000
#define THR2 (0.01f * 0.01f)
#define MAX_IT 10

typedef __nv_bfloat16 bf16;

// ---------------- scratch (__device__ globals) ------------------------------
__device__ float g_base[NN * 512];
__device__ float g_H[NN * 512];
__device__ float g_state[NN * 128];
__device__ float g_new[NN * 128];
__device__ int   g_cnt[NN];
__device__ int   g_ptr_adj[NN + 1];
__device__ int   g_ptr_an[NN + 1];
__device__ int   g_src_adj[EE];
__device__ float g_val_adj[EE];
__device__ int   g_eid_an[EE];
__device__ float g_val_an[EE];
__device__ int   g_flag;
__device__ int   g_done;
__device__ int   g_cont;

// bf16 split operands (16B aligned for cp.async / vector access)
__device__ __align__(16) bf16 g_ws1t_h[512 * 576];
__device__ __align__(16) bf16 g_ws1t_l[512 * 576];
__device__ __align__(16) bf16 g_ws2t_h[128 * 512];
__device__ __align__(16) bf16 g_ws2t_l[128 * 512];
__device__ __align__(16) bf16 g_wo1t_h[512 * 256];
__device__ __align__(16) bf16 g_wo1t_l[512 * 256];
__device__ __align__(16) bf16 g_nodes_h[NN * 128];
__device__ __align__(16) bf16 g_nodes_l[NN * 128];
__device__ __align__(16) bf16 g_aggn_h[NN * 128];
__device__ __align__(16) bf16 g_aggn_l[NN * 128];
__device__ __align__(16) bf16 g_agga_h[NN * 64];
__device__ __align__(16) bf16 g_agga_l[NN * 64];
__device__ __align__(16) bf16 g_state_h[NN * 128];
__device__ __align__(16) bf16 g_state_l[NN * 128];
__device__ __align__(16) bf16 g_aggs_h[NN * 128];
__device__ __align__(16) bf16 g_aggs_l[NN * 128];
__device__ __align__(16) bf16 g_Hh[NN * 512];
__device__ __align__(16) bf16 g_Hl[NN * 512];

// ---------------- helpers ---------------------------------------------------
#define SWZ(o) ((o) ^ (((o) >> 3) & 0x70))

#define CP16(dst, src, sz) \
    asm volatile("cp.async.cg.shared.global [%0], [%1], 16, %2;" \
                 :: "r"(dst), "l"(src), "r"(sz) : "memory")
#define CP_COMMIT() asm volatile("cp.async.commit_group;" ::: "memory")

#define LDSM4(r0, r1, r2, r3, addr) \
    asm volatile("ldmatrix.sync.aligned.m8n8.x4.shared.b16 {%0,%1,%2,%3}, [%4];" \
                 : "=r"(r0), "=r"(r1), "=r"(r2), "=r"(r3) : "r"(addr))

__device__ __forceinline__ void mma16816(float* d, const uint32_t* a, const uint32_t* b) {
    asm volatile("mma.sync.aligned.m16n8k16.row.col.f32.bf16.bf16.f32 "
                 "{%0,%1,%2,%3}, {%4,%5,%6,%7}, {%8,%9}, {%0,%1,%2,%3};"
                 : "+f"(d[0]), "+f"(d[1]), "+f"(d[2]), "+f"(d[3])
                 : "r"(a[0]), "r"(a[1]), "r"(a[2]), "r"(a[3]), "r"(b[0]), "r"(b[1]));
}

__device__ __forceinline__ float fast_tanh(float x) {
    float ax = fabsf(x);
    float e = __expf(-2.f * ax);
    float r = __fdividef(1.f - e, 1.f + e);
    return copysignf(r, x);
}

// pack (x,y) into hi-bf16x2, return; lo residual pair in lopack
__device__ __forceinline__ uint32_t packpair(float x, float y, uint32_t& lopack) {
    bf16 hx = __float2bfloat16(x);
    bf16 hy = __float2bfloat16(y);
    float rx = x - __bfloat162float(hx);
    float ry = y - __bfloat162float(hy);
    bf16 lx = __float2bfloat16(rx);
    bf16 ly = __float2bfloat16(ry);
    lopack = ((uint32_t)__bfloat16_as_ushort(ly) << 16) | __bfloat16_as_ushort(lx);
    return ((uint32_t)__bfloat16_as_ushort(hy) << 16) | __bfloat16_as_ushort(hx);
}

// ---------------- CSR build -------------------------------------------------
__global__ void hist_kernel(const int* __restrict__ dst, int e) {
    int i = blockIdx.x * blockDim.x + threadIdx.x;
    if (i < e) atomicAdd(&g_cnt[dst[i]], 1);
}

__global__ void scan_kernel(const int* __restrict__ cnt, int* __restrict__ ptr, int n) {
    __shared__ int sh[1024];
    __shared__ int carry;
    int t = threadIdx.x;
    if (t == 0) { carry = 0; ptr[0] = 0; }
    __syncthreads();
    for (int base = 0; base < n; base += 1024) {
        int x = (base + t < n) ? cnt[base + t] : 0;
        sh[t] = x;
        __syncthreads();
        for (int off = 1; off < 1024; off <<= 1) {
            int y = (t >= off) ? sh[t - off] : 0;
            __syncthreads();
            sh[t] += y;
            __syncthreads();
        }
        if (base + t < n) ptr[base + t + 1] = carry + sh[t];
        __syncthreads();
        if (t == 0) carry += sh[1023];
        __syncthreads();
    }
}

__global__ void scatter_adj_kernel(const int* __restrict__ src, const int* __restrict__ dst,
                                   const float* __restrict__ vals, int e) {
    int i = blockIdx.x * blockDim.x + threadIdx.x;
    if (i < e) {
        int d = dst[i];
        int pos = g_ptr_adj[d] + atomicAdd(&g_cnt[d], 1);
        g_src_adj[pos] = src[i];
        g_val_adj[pos] = vals[i];
    }
}

__global__ void scatter_an_kernel(const int* __restrict__ dst, const float* __restrict__ vals, int e) {
    int i = blockIdx.x * blockDim.x + threadIdx.x;
    if (i < e) {
        int d = dst[i];
        int pos = g_ptr_an[d] + atomicAdd(&g_cnt[d], 1);
        g_eid_an[pos] = i;
        g_val_an[pos] = vals[i];
    }
}

// ---------------- converters -------------------------------------------------
// W[K,N] fp32 -> Wt[N,K] bf16 hi/lo
__global__ void convert_wt_kernel(const float* __restrict__ W, int K, int N,
                                  bf16* __restrict__ hi, bf16* __restrict__ lo) {
    int idx = blockIdx.x * blockDim.x + threadIdx.x;
    if (idx >= K * N) return;
    int k = idx / N, n = idx % N;
    float x = W[idx];
    bf16 h = __float2bfloat16(x);
    hi[(size_t)n * K + k] = h;
    lo[(size_t)n * K + k] = __float2bfloat16(x - __bfloat162float(h));
}

// elementwise split fp32 -> hi/lo (same layout)
__global__ void split_kernel(const float* __restrict__ X, int cnt,
                             bf16* __restrict__ hi, bf16* __restrict__ lo) {
    int i = blockIdx.x * blockDim.x + threadIdx.x;
    if (i * 2 >= cnt) return;
    float2 v = *(const float2*)(X + i * 2);
    uint32_t l, h = packpair(v.x, v.y, l);
    *(uint32_t*)((char*)hi + (size_t)i * 4) = h;
    *(uint32_t*)((char*)lo + (size_t)i * 4) = l;
}

// ---------------- SPMM (writes bf16 split) ----------------------------------
__global__ void spmm128_kernel(const int* __restrict__ ptr, const int* __restrict__ srcs,
                               const float* __restrict__ vals, const float* __restrict__ dense,
                               bf16* __restrict__ oh, bf16* __restrict__ ol,
                               int n, const int* gate) {
    if (gate && *gate == 0) return;
    int w = (blockIdx.x * blockDim.x + threadIdx.x) >> 5;
    int lane = threadIdx.x & 31;
    if (w >= n) return;
    int s = ptr[w], t = ptr[w + 1];
    float ax = 0.f, ay = 0.f, az = 0.f, aw = 0.f;
    for (int e = s; e < t; e++) {
        float v = vals[e];
        int src = srcs[e];
        float4 x = *(const float4*)(dense + (size_t)src * 128 + lane * 4);
        ax += v * x.x; ay += v * x.y; az += v * x.z; aw += v * x.w;
    }
    uint2 hp, lp;
    hp.x = packpair(ax, ay, lp.x);
    hp.y = packpair(az, aw, lp.y);
    *(uint2*)(oh + (size_t)w * 128 + lane * 4) = hp;
    *(uint2*)(ol + (size_t)w * 128 + lane * 4) = lp;
}

__global__ void spmm_arcs_kernel(const float* __restrict__ arcs, int n) {
    int w = (blockIdx.x * blockDim.x + threadIdx.x) >> 5;
    int lane = threadIdx.x & 31;
    if (w >= n) return;
    int s = g_ptr_an[w], t = g_ptr_an[w + 1];
    float ax = 0.f, ay = 0.f;
    for (int e = s; e < t; e++) {
        float v = g_val_an[e];
        int eid = g_eid_an[e];
        float2 x = *(const float2*)(arcs + (size_t)eid * 66 + 2 + lane * 2);
        ax += v * x.x; ay += v * x.y;
    }
    uint32_t lp, hp = packpair(ax, ay, lp);
    *(uint32_t*)(g_agga_h + (size_t)w * 64 + lane * 2) = hp;
    *(uint32_t*)(g_agga_l + (size_t)w * 64 + lane * 2) = lp;
}

// ---------------- state init / convergence / update ------------------------
__global__ void reset_kernel() {
    if (threadIdx.x == 0) { g_flag = 0; g_done = 0; g_cont = 0; }
}

__global__ void init_kernel(const float* __restrict__ si, int n) {
    int w = (blockIdx.x * blockDim.x + threadIdx.x) >> 5;
    int lane = threadIdx.x & 31;
    if (w >= n) return;
    float4 st = *(const float4*)(si + (size_t)w * 128 + lane * 4);
    *(float4*)(g_state + (size_t)w * 128 + lane * 4) = st;
    uint2 hp, lp;
    hp.x = packpair(st.x, st.y, lp.x);
    hp.y = packpair(st.z, st.w, lp.y);
    *(uint2*)(g_state_h + (size_t)w * 128 + lane * 4) = hp;
    *(uint2*)(g_state_l + (size_t)w * 128 + lane * 4) = lp;
    float dx = st.x - 1.f, dy = st.y - 1.f, dz = st.z - 1.f, dw = st.w - 1.f;
    float d2 = dx * dx + dy * dy + dz * dz + dw * dw;
    #pragma unroll
    for (int s = 16; s > 0; s >>= 1) d2 += __shfl_xor_sync(0xffffffffu, d2, s);
    if (lane == 0 && d2 > THR2 * 128.f) atomicOr(&g_flag, 1);
}

__global__ void finalize_kernel() {
    if (threadIdx.x == 0) {
        int c = (g_flag && !g_done) ? 1 : 0;
        g_cont = c;
        g_done = c ? 0 : 1;
        g_flag = 0;
    }
}

__global__ void update_kernel(int n, const int* gate) {
    if (*gate == 0) return;
    int w = (blockIdx.x * blockDim.x + threadIdx.x) >> 5;
    int lane = threadIdx.x & 31;
    if (w >= n) return;
    float4 st = *(const float4*)(g_state + (size_t)w * 128 + lane * 4);
    float4 nw = *(const float4*)(g_new + (size_t)w * 128 + lane * 4);
    float dx = nw.x - st.x, dy = nw.y - st.y, dz = nw.z - st.z, dw = nw.w - st.w;
    float d2 = dx * dx + dy * dy + dz * dz + dw * dw;
    float n2 = st.x * st.x + st.y * st.y + st.z * st.z + st.w * st.w;
    #pragma unroll
    for (int s = 16; s > 0; s >>= 1) {
        d2 += __shfl_xor_sync(0xffffffffu, d2, s);
        n2 += __shfl_xor_sync(0xffffffffu, n2, s);
    }
    *(float4*)(g_state + (size_t)w * 128 + lane * 4) = nw;
    uint2 hp, lp;
    hp.x = packpair(nw.x, nw.y, lp.x);
    hp.y = packpair(nw.z, nw.w, lp.y);
    *(uint2*)(g_state_h + (size_t)w * 128 + lane * 4) = hp;
    *(uint2*)(g_state_l + (size_t)w * 128 + lane * 4) = lp;
    if (lane == 0 && d2 > THR2 * n2) atomicOr(&g_flag, 1);
}

// ---------------- mma.sync bf16x3 GEMM --------------------------------------
// C[M x N] = act( addend + bias + sum_segs A_s @ B_s^T )
// A pre-split bf16 hi/lo [M,K] row-major; B pre-split [N,K] row-major.
// CTA tile 128x128, BK=32, 8 warps (warp tile 32x64), 2-stage cp.async pipeline.
// smem per buffer: A 128 rows x [hi32|lo32] bf16 (128B, SW128) = 16KB, B same.
#define GEMM_SMEM 65536

__global__ void __launch_bounds__(256, 1) gemm_mma_kernel(
    int M,
    const bf16* __restrict__ A0h, const bf16* __restrict__ A0l, int lda0, int K0, int bofs0,
    const bf16* __restrict__ A1h, const bf16* __restrict__ A1l, int lda1, int K1, int bofs1,
    const bf16* __restrict__ A2h, const bf16* __restrict__ A2l, int lda2, int K2, int bofs2,
    const bf16* __restrict__ Bh, const bf16* __restrict__ Bl, int ldb,
    const float* __restrict__ addend, int ldadd,
    const float* __restrict__ bias, int do_tanh,
    float* __restrict__ Cf, bf16* __restrict__ Ch, bf16* __restrict__ Cl, int ldc,
    const int* gate)
{
    if (gate && *gate == 0) return;
    extern __shared__ char smem_raw[];
    const uint32_t sm0 = (uint32_t)__cvta_generic_to_shared(smem_raw);

    const int tid = threadIdx.x;
    const int wid = tid >> 5;
    const int lane = tid & 31;
    const int bm = blockIdx.x * 128;
    const int bn = blockIdx.y * 128;
    const int warp_m = (wid & 3) * 32;
    const int warp_n = (wid >> 2) * 64;

    // staging coords
    const int r = tid >> 1;
    const int half = tid & 1;
    const int grow = bm + r;
    const bool rowok = grow < M;
    const int arow = rowok ? grow : (M - 1);

    const bf16* segAh[3] = {A0h, A1h, A2h};
    const bf16* segAl[3] = {A0l, A1l, A2l};
    const int segLda[3] = {lda0, lda1, lda2};
    const int segBofs[3] = {bofs0, bofs1, bofs2};
    const int c0 = K0 / 32;
    const int c01 = c0 + K1 / 32;
    const int total = c01 + K2 / 32;

    float acc[2][8][4];
    #pragma unroll
    for (int i = 0; i < 2; i++)
        #pragma unroll
        for (int j = 0; j < 8; j++)
            #pragma unroll
            for (int q = 0; q < 4; q++) acc[i][j][q] = 0.f;

    auto stage = [&](int ci, int buf) {
        int s, kb;
        if (ci < c0) { s = 0; kb = ci * 32; }
        else if (ci < c01) { s = 1; kb = (ci - c0) * 32; }
        else { s = 2; kb = (ci - c01) * 32; }
        uint32_t ab = sm0 + buf * 32768;
        uint32_t bb = ab + 16384;
        {
            const bf16* src = half ? segAl[s] : segAh[s];
            const char* g = (const char*)(src + (size_t)arow * segLda[s] + kb);
            uint32_t sz = rowok ? 16u : 0u;
            #pragma unroll
            for (int c = 0; c < 4; c++) {
                uint32_t dst = ab + SWZ((uint32_t)(r * 128 + (half * 4 + c) * 16));
                CP16(dst, g + c * 16, sz);
            }
        }
        {
            const bf16* src = half ? Bl : Bh;
            const char* g = (const char*)(src + (size_t)(bn + r) * ldb + segBofs[s] + kb);
            #pragma unroll
            for (int c = 0; c < 4; c++) {
                uint32_t dst = bb + SWZ((uint32_t)(r * 128 + (half * 4 + c) * 16));
                CP16(dst, g + c * 16, 16u);
            }
        }
        CP_COMMIT();
    };

    stage(0, 0);
    for (int ci = 0; ci < total; ci++) {
        int buf = ci & 1;
        bool hasnext = (ci + 1) < total;
        if (hasnext) stage(ci + 1, buf ^ 1);
        if (hasnext) asm volatile("cp.async.wait_group 1;" ::: "memory");
        else asm volatile("cp.async.wait_group 0;" ::: "memory");
        __syncthreads();

        uint32_t ab = sm0 + buf * 32768;
        uint32_t bb = ab + 16384;
        #pragma unroll
        for (int k16 = 0; k16 < 2; k16++) {
            uint32_t ah[2][4], al[2][4], bhf[8][2], blf[8][2];
            #pragma unroll
            for (int i = 0; i < 2; i++) {
                uint32_t rowA = warp_m + i * 16 + (lane & 7) + ((lane >> 3) & 1) * 8;
                uint32_t ch = k16 * 2 + (lane >> 4);
                uint32_t ad = ab + SWZ(rowA * 128 + ch * 16);
                LDSM4(ah[i][0], ah[i][1], ah[i][2], ah[i][3], ad);
                uint32_t adl = ab + SWZ(rowA * 128 + (ch + 4) * 16);
                LDSM4(al[i][0], al[i][1], al[i][2], al[i][3], adl);
            }
            #pragma unroll
            for (int jp = 0; jp < 4; jp++) {
                uint32_t rowB = warp_n + jp * 16 + ((lane >> 4) << 3) + (lane & 7);
                uint32_t ch = k16 * 2 + ((lane >> 3) & 1);
                uint32_t t0, t1, t2, t3;
                uint32_t bd = bb + SWZ(rowB * 128 + ch * 16);
                LDSM4(t0, t1, t2, t3, bd);
                bhf[2 * jp][0] = t0; bhf[2 * jp][1] = t1;
                bhf[2 * jp + 1][0] = t2; bhf[2 * jp + 1][1] = t3;
                uint32_t bdl = bb + SWZ(rowB * 128 + (ch + 4) * 16);
                LDSM4(t0, t1, t2, t3, bdl);
                blf[2 * jp][0] = t0; blf[2 * jp][1] = t1;
                blf[2 * jp + 1][0] = t2; blf[2 * jp + 1][1] = t3;
            }
            #pragma unroll
            for (int i = 0; i < 2; i++)
                #pragma unroll
                for (int j = 0; j < 8; j++) {
                    mma16816(acc[i][j], ah[i], bhf[j]);
                    mma16816(acc[i][j], ah[i], blf[j]);
                    mma16816(acc[i][j], al[i], bhf[j]);
                }
        }
        __syncthreads();
    }

    // epilogue
    const int gr = lane >> 2;
    const int gc = (lane & 3) * 2;
    #pragma unroll
    for (int i = 0; i < 2; i++) {
        #pragma unroll
        for (int hf = 0; hf < 2; hf++) {
            int row = bm + warp_m + i * 16 + hf * 8 + gr;
            if (row >= M) continue;
            #pragma unroll
            for (int j = 0; j < 8; j++) {
                int col = bn + warp_n + j * 8 + gc;
                float vx = acc[i][j][hf * 2 + 0];
                float vy = acc[i][j][hf * 2 + 1];
                if (addend) {
                    float2 b = *(const float2*)(addend + (size_t)row * ldadd + col);
                    vx += b.x; vy += b.y;
                }
                if (bias) {
                    float2 b = *(const float2*)(bias + col);
                    vx += b.x; vy += b.y;
                }
                if (do_tanh) { vx = fast_tanh(vx); vy = fast_tanh(vy); }
                if (Cf) {
                    float2 o; o.x = vx; o.y = vy;
                    *(float2*)(Cf + (size_t)row * ldc + col) = o;
                }
                if (Ch) {
                    uint32_t lp, hp = packpair(vx, vy, lp);
                    *(uint32_t*)(Ch + (size_t)row * ldc + col) = hp;
                    *(uint32_t*)(Cl + (size_t)row * ldc + col) = lp;
                }
            }
        }
    }
}

// ---------------- final projection (N x 512 @ 512 x 7) ----------------------
__global__ void out_kernel(const float* __restrict__ Hout, const float* __restrict__ Wo2,
                           const float* __restrict__ bo2, const int* __restrict__ m1,
                           const int* __restrict__ m2, float* __restrict__ out, int n) {
    __shared__ float w[512 * 7];
    for (int i = threadIdx.x; i < 512 * 7; i += blockDim.x) w[i] = Wo2[i];
    __syncthreads();
    int wrp = (blockIdx.x * blockDim.x + threadIdx.x) >> 5;
    int lane = threadIdx.x & 31;
    if (wrp >= n) return;
    const float* h = Hout + (size_t)wrp * 512;
    float acc[7] = {0.f, 0.f, 0.f, 0.f, 0.f, 0.f, 0.f};
    for (int t = 0; t < 16; t++) {
        int k = t * 32 + lane;
        float x = h[k];
        #pragma unroll
        for (int o = 0; o < 7; o++) acc[o] += x * w[k * 7 + o];
    }
    #pragma unroll
    for (int o = 0; o < 7; o++) {
        #pragma unroll
        for (int s = 16; s > 0; s >>= 1) acc[o] += __shfl_xor_sync(0xffffffffu, acc[o], s);
    }
    if (lane == 0) {
        float mk = (m1[wrp] != 0 && m2[wrp] != 0) ? 1.f : 0.f;
        #pragma unroll
        for (int o = 0; o < 7; o++) out[(size_t)wrp * 7 + o] = (acc[o] + bo2[o]) * mk;
    }
}

// ---------------- host ------------------------------------------------------
extern "C" void kernel_launch(void* const* d_in, const int* in_sizes, int n_in,
                              void* d_out, int out_size) {
    const float* nodes       = (const float*)d_in[0];
    const float* arcs        = (const float*)d_in[1];
    const int*   set_mask    = (const int*)d_in[2];
    const int*   output_mask = (const int*)d_in[3];
    const int*   adj_src     = (const int*)d_in[4];
    const int*   adj_dst     = (const int*)d_in[5];
    const float* adj_vals    = (const float*)d_in[6];
    const int*   an_dst      = (const int*)d_in[7];
    const float* an_vals     = (const float*)d_in[8];
    const float* state_init  = (const float*)d_in[9];
    const float* Ws1         = (const float*)d_in[10];
    const float* bs1         = (const float*)d_in[11];
    const float* Ws2         = (const float*)d_in[12];
    const float* bs2         = (const float*)d_in[13];
    const float* Wo1         = (const float*)d_in[14];
    const float* bo1         = (const float*)d_in[15];
    const float* Wo2         = (const float*)d_in[16];
    const float* bo2         = (const float*)d_in[17];

    const int n = NN;
    const int e = EE;

    float *p_base, *p_H, *p_state, *p_new, *p_val_adj;
    int *p_cnt, *p_ptr_adj, *p_ptr_an, *p_src_adj, *p_cont;
    bf16 *p_ws1h, *p_ws1l, *p_ws2h, *p_ws2l, *p_wo1h, *p_wo1l;
    bf16 *p_ndh, *p_ndl, *p_anh, *p_anl, *p_aah, *p_aal;
    bf16 *p_sth, *p_stl, *p_ash, *p_asl, *p_Hh, *p_Hl;
    cudaGetSymbolAddress((void**)&p_base, g_base);
    cudaGetSymbolAddress((void**)&p_H, g_H);
    cudaGetSymbolAddress((void**)&p_state, g_state);
    cudaGetSymbolAddress((void**)&p_new, g_new);
    cudaGetSymbolAddress((void**)&p_cnt, g_cnt);
    cudaGetSymbolAddress((void**)&p_ptr_adj, g_ptr_adj);
    cudaGetSymbolAddress((void**)&p_ptr_an, g_ptr_an);
    cudaGetSymbolAddress((void**)&p_src_adj, g_src_adj);
    cudaGetSymbolAddress((void**)&p_val_adj, g_val_adj);
    cudaGetSymbolAddress((void**)&p_cont, g_cont);
    cudaGetSymbolAddress((void**)&p_ws1h, g_ws1t_h);
    cudaGetSymbolAddress((void**)&p_ws1l, g_ws1t_l);
    cudaGetSymbolAddress((void**)&p_ws2h, g_ws2t_h);
    cudaGetSymbolAddress((void**)&p_ws2l, g_ws2t_l);
    cudaGetSymbolAddress((void**)&p_wo1h, g_wo1t_h);
    cudaGetSymbolAddress((void**)&p_wo1l, g_wo1t_l);
    cudaGetSymbolAddress((void**)&p_ndh, g_nodes_h);
    cudaGetSymbolAddress((void**)&p_ndl, g_nodes_l);
    cudaGetSymbolAddress((void**)&p_anh, g_aggn_h);
    cudaGetSymbolAddress((void**)&p_anl, g_aggn_l);
    cudaGetSymbolAddress((void**)&p_aah, g_agga_h);
    cudaGetSymbolAddress((void**)&p_aal, g_agga_l);
    cudaGetSymbolAddress((void**)&p_sth, g_state_h);
    cudaGetSymbolAddress((void**)&p_stl, g_state_l);
    cudaGetSymbolAddress((void**)&p_ash, g_aggs_h);
    cudaGetSymbolAddress((void**)&p_asl, g_aggs_l);
    cudaGetSymbolAddress((void**)&p_Hh, g_Hh);
    cudaGetSymbolAddress((void**)&p_Hl, g_Hl);

    cudaFuncSetAttribute(gemm_mma_kernel, cudaFuncAttributeMaxDynamicSharedMemorySize,
                         GEMM_SMEM);

    const int gbE = (e + 255) / 256;
    const int gbW = (n * 32 + 255) / 256;
    const int gbM = (n + 127) / 128;

    // ---- one-time weight/feature conversions ----
    convert_wt_kernel<<<(576 * 512 + 255) / 256, 256>>>(Ws1, 576, 512, p_ws1h, p_ws1l);
    convert_wt_kernel<<<(512 * 128 + 255) / 256, 256>>>(Ws2, 512, 128, p_ws2h, p_ws2l);
    convert_wt_kernel<<<(256 * 512 + 255) / 256, 256>>>(Wo1, 256, 512, p_wo1h, p_wo1l);
    split_kernel<<<(n * 64 + 255) / 256, 256>>>(nodes, n * 128, p_ndh, p_ndl);

    // ---- CSR builds ----
    cudaMemsetAsync(p_cnt, 0, n * sizeof(int));
    hist_kernel<<<gbE, 256>>>(an_dst, e);
    scan_kernel<<<1, 1024>>>(p_cnt, p_ptr_an, n);
    cudaMemsetAsync(p_cnt, 0, n * sizeof(int));
    scatter_an_kernel<<<gbE, 256>>>(an_dst, an_vals, e);

    cudaMemsetAsync(p_cnt, 0, n * sizeof(int));
    hist_kernel<<<gbE, 256>>>(adj_dst, e);
    scan_kernel<<<1, 1024>>>(p_cnt, p_ptr_adj, n);
    cudaMemsetAsync(p_cnt, 0, n * sizeof(int));
    scatter_adj_kernel<<<gbE, 256>>>(adj_src, adj_dst, adj_vals, e);

    // ---- loop-invariant aggregations (written as bf16 split) ----
    spmm_arcs_kernel<<<gbW, 256>>>(arcs, n);
    spmm128_kernel<<<gbW, 256>>>(p_ptr_adj, p_src_adj, p_val_adj, nodes, p_anh, p_anl, n, nullptr);

    // ---- state init + invariant part of GEMM1 (Ws1 cols 128..575) ----
    reset_kernel<<<1, 32>>>();
    init_kernel<<<gbW, 256>>>(state_init, n);
    gemm_mma_kernel<<<dim3(gbM, 4), 256, GEMM_SMEM>>>(
        n,
        p_ndh, p_ndl, 128, 128, 128,
        p_anh, p_anl, 128, 128, 384,
        p_aah, p_aal, 64, 64, 512,
        p_ws1h, p_ws1l, 576,
        nullptr, 0, bs1, 0,
        p_base, nullptr, nullptr, 512,
        nullptr);

    // ---- fixed-point iterations ----
    for (int it = 0; it < MAX_IT; it++) {
        finalize_kernel<<<1, 32>>>();
        spmm128_kernel<<<gbW, 256>>>(p_ptr_adj, p_src_adj, p_val_adj, p_state, p_ash, p_asl, n, p_cont);
        gemm_mma_kernel<<<dim3(gbM, 4), 256, GEMM_SMEM>>>(
            n,
            p_sth, p_stl, 128, 128, 0,
            p_ash, p_asl, 128, 128, 256,
            nullptr, nullptr, 0, 0, 0,
            p_ws1h, p_ws1l, 576,
            p_base, 512, nullptr, 1,
            nullptr, p_Hh, p_Hl, 512,
            p_cont);
        gemm_mma_kernel<<<dim3(gbM, 1), 256, GEMM_SMEM>>>(
            n,
            p_Hh, p_Hl, 512, 512, 0,
            nullptr, nullptr, 0, 0, 0,
            nullptr, nullptr, 0, 0, 0,
            p_ws2h, p_ws2l, 512,
            nullptr, 0, bs2, 1,
            p_new, nullptr, nullptr, 128,
            p_cont);
        update_kernel<<<gbW, 256>>>(n, p_cont);
    }

    // ---- output head ----
    gemm_mma_kernel<<<dim3(gbM, 4), 256, GEMM_SMEM>>>(
        n,
        p_sth, p_stl, 128, 128, 0,
        p_ndh, p_ndl, 128, 128, 128,
        nullptr, nullptr, 0, 0, 0,
        p_wo1h, p_wo1l, 256,
        nullptr, 0, bo1, 1,
        p_H, nullptr, nullptr, 512,
        nullptr);
    out_kernel<<<gbW, 256>>>(p_H, Wo2, bo2, set_mask, output_mask, (float*)d_out, n);
}